// round 15
// baseline (speedup 1.0000x reference)
#include <cuda_runtime.h>
#include <cuda_bf16.h>
#include <math.h>

#define N_PROP   65536
#define N_GT     64
#define NCLS     81
#define TOTAL    512
#define MAX_POS  128
#define TPB      1024
#define NBLK     128
#define PPB      512
#define NCHUNK   256            // chunks of 256 proposals

// -------- device scratch --------
__device__ unsigned char g_resb[N_PROP];   // f | (gt<<2)
__device__ int   g_ckp[NCHUNK];
__device__ int   g_ckn[NCHUNK];
__device__ unsigned long long g_acc_ce;    // fixed-point 2^32 accumulators
__device__ unsigned long long g_acc_rg;
__device__ int          g_cntA[32];
__device__ volatile int g_genA[32];
__device__ int          g_done;

__device__ __forceinline__ float sl1(float d) {
    float ad = fabsf(d);
    return (ad < 1.0f) ? (0.5f * d * d) : (ad - 0.5f);
}

__global__ void __launch_bounds__(TPB, 1)
k_fused(const float* __restrict__ props,
        const float* __restrict__ gts,
        const int*   __restrict__ gt_labels,
        const float* __restrict__ score,
        const float* __restrict__ txty,
        float* __restrict__ out) {
    __shared__ float4 sg[N_GT];
    __shared__ float  sS[N_GT];
    __shared__ float  sga[N_GT];
    __shared__ int    slbl[N_GT];
    __shared__ float  s_ci[PPB], s_cu[PPB];
    __shared__ int    s_cj[PPB];
    __shared__ int    wpc[16], wnc[16];
    __shared__ int    swp[8], swn[8];
    __shared__ int    ssp[NCHUNK], ssn[NCHUNK];   // inclusive scans
    __shared__ int    s_numpos, s_negtot;
    __shared__ int    s_last;

    const int t    = threadIdx.x;
    const int bid  = blockIdx.x;
    const int warp = t >> 5, lane = t & 31;
    const int half = t >> 9;
    const int lp   = t & (PPB - 1);
    const unsigned full = 0xffffffffu;

    // ---- stage gt data ----
    if (t < N_GT) {
        float4 g = ((const float4*)gts)[t];
        float ga = (g.z - g.x) * (g.w - g.y);
        sg[t]  = g;
        sga[t] = ga;
        sS[t]  = ga + 1e-8f;
        slbl[t] = gt_labels[t];
    }
    __syncthreads();

    // ============ phase 1: IoU argmax (proven) ============
    const int i = bid * PPB + lp;
    const float4 p = ((const float4*)props)[i];
    const float pa = (p.z - p.x) * (p.w - p.y);

    const int j0 = half * 32;
    float biA, bSA, biB, bSB;
    int   bjA, bjB;
    {
        float4 g = sg[j0];
        float ix = fmaxf(fminf(p.z, g.z) - fmaxf(p.x, g.x), 0.f);
        float iy = fmaxf(fminf(p.w, g.w) - fmaxf(p.y, g.y), 0.f);
        biA = ix * iy; bSA = pa + sS[j0]; bjA = j0;
        g = sg[j0 + 16];
        ix = fmaxf(fminf(p.z, g.z) - fmaxf(p.x, g.x), 0.f);
        iy = fmaxf(fminf(p.w, g.w) - fmaxf(p.y, g.y), 0.f);
        biB = ix * iy; bSB = pa + sS[j0 + 16]; bjB = j0 + 16;
    }
#pragma unroll
    for (int j = 1; j < 16; j++) {
        int jA = j0 + j, jB = j0 + 16 + j;
        float4 gA = sg[jA], gB = sg[jB];
        float SA = pa + sS[jA], SB = pa + sS[jB];
        float ixA = fmaxf(fminf(p.z, gA.z) - fmaxf(p.x, gA.x), 0.f);
        float iyA = fmaxf(fminf(p.w, gA.w) - fmaxf(p.y, gA.y), 0.f);
        float ixB = fmaxf(fminf(p.z, gB.z) - fmaxf(p.x, gB.x), 0.f);
        float iyB = fmaxf(fminf(p.w, gB.w) - fmaxf(p.y, gB.y), 0.f);
        float inA = ixA * iyA, inB = ixB * iyB;
        // iou_new > iou_best <=> in*bS > bi*S (union -inter terms cancel exactly)
        if (inA * bSA > biA * SA) { biA = inA; bSA = SA; bjA = jA; }
        if (inB * bSB > biB * SB) { biB = inB; bSB = SB; bjB = jB; }
    }
    if (biB * bSA > biA * bSB) { biA = biB; bSA = bSB; bjA = bjB; }

    if (half == 1) { s_ci[lp] = biA; s_cu[lp] = bSA; s_cj[lp] = bjA; }
    __syncthreads();

    int f = 0;
    unsigned bp = 0, bn = 0;
    if (half == 0) {
        float ui = s_ci[lp], uS = s_cu[lp];
        if (ui * bSA > biA * uS) { biA = ui; bSA = uS; bjA = s_cj[lp]; }
        float u = ((pa + sga[bjA]) - biA) + 1e-8f;   // exact reference assoc order
        float miou = biA / u;
        f = (miou >= 0.5f) ? 1 : ((miou >= 0.1f) ? 2 : 0);
        g_resb[i] = (unsigned char)(f | (bjA << 2));
        bp = __ballot_sync(full, f == 1);
        bn = __ballot_sync(full, f == 2);
        if (lane == 0) { wpc[warp] = __popc(bp); wnc[warp] = __popc(bn); }
    }
    __syncthreads();
    if (t < 2) {        // chunk counts: warps 0-7 -> chunk 2bid, 8-15 -> 2bid+1
        int cp = 0, cn = 0;
#pragma unroll
        for (int w = 0; w < 8; w++) { cp += wpc[t * 8 + w]; cn += wnc[t * 8 + w]; }
        g_ckp[2 * bid + t] = cp;
        g_ckn[2 * bid + t] = cn;
    }

    // ============ barrier A (the ONLY spin barrier) ============
    __syncthreads();
    if (t == 0) {
        __threadfence();
        if (atomicAdd(&g_cntA[0], 1) == NBLK - 1) {
            __threadfence();
            g_genA[0] = 1;
        } else {
            while (g_genA[0] == 0) { }
            __threadfence();
        }
    }
    __syncthreads();

    // ============ scan 256 chunk counts (warps 0-7) ============
    if (t < NCHUNK) {
        int ip  = __ldcg(&g_ckp[t]);
        int in_ = __ldcg(&g_ckn[t]);
#pragma unroll
        for (int o = 1; o < 32; o <<= 1) {
            int a = __shfl_up_sync(full, ip, o);
            int b = __shfl_up_sync(full, in_, o);
            if (lane >= o) { ip += a; in_ += b; }
        }
        if (lane == 31) { swp[warp] = ip; swn[warp] = in_; }
        __syncthreads();
        int basep = 0, basen = 0;
        for (int w = 0; w < warp; w++) { basep += swp[w]; basen += swn[w]; }
        ssp[t] = basep + ip;
        ssn[t] = basen + in_;
    } else {
        __syncthreads();
    }
    __syncthreads();
    if (t == 0) {
        s_numpos = min(ssp[NCHUNK - 1], MAX_POS);
        s_negtot = ssn[NCHUNK - 1];
    }
    __syncthreads();

    // ============ resolve + loss: warps 0-3 own slots 4bid+w ============
    if (warp < 4) {
        const int slot = bid * 4 + warp;
        const int npos = s_numpos, negt = s_negtot;
        int mode, r;
        bool is_pos = slot < npos;
        if (is_pos)                  { mode = 0; r = slot; }
        else if (slot < npos + negt) { mode = 1; r = slot - npos; }
        else                         { mode = 2; r = slot - npos - negt; }

        // find owning chunk (lane-parallel over 256 chunks)
        int found = 0;
#pragma unroll
        for (int k = 0; k < 8; k++) {
            int c = lane + 32 * k;
            int sp0 = (c > 0) ? ssp[c - 1] : 0;
            int sn0 = (c > 0) ? ssn[c - 1] : 0;
            int cb, ce_;
            if (mode == 0)      { cb = sp0;           ce_ = ssp[c]; }
            else if (mode == 1) { cb = sn0;           ce_ = ssn[c]; }
            else                { cb = c * 256 - sn0; ce_ = (c + 1) * 256 - ssn[c]; }
            if (cb <= r && r < ce_) found = c + 1;
        }
#pragma unroll
        for (int o = 16; o; o >>= 1) found = max(found, __shfl_xor_sync(full, found, o));
        const int c = found - 1;
        int cb;
        {
            int sp0 = (c > 0) ? ssp[c - 1] : 0;
            int sn0 = (c > 0) ? ssn[c - 1] : 0;
            cb = (mode == 0) ? sp0 : (mode == 1) ? sn0 : (c * 256 - sn0);
        }
        const int need_rank = r - cb;

        // load chunk flags: 256 bytes = 64 ints; lane l takes words 2l, 2l+1
        const int* cw = (const int*)g_resb + c * 64;
        int w0 = __ldcg(&cw[2 * lane]);
        int w1 = __ldcg(&cw[2 * lane + 1]);
        int myc;
        if (mode == 0)      myc = __popc(w0 & 0x01010101) + __popc(w1 & 0x01010101);
        else if (mode == 1) myc = __popc(w0 & 0x02020202) + __popc(w1 & 0x02020202);
        else                myc = 8 - __popc(w0 & 0x02020202) - __popc(w1 & 0x02020202);
        int ex = myc;
#pragma unroll
        for (int o = 1; o < 32; o <<= 1) {
            int a = __shfl_up_sync(full, ex, o);
            if (lane >= o) ex += a;
        }
        ex -= myc;
        int ent = 0;
        if (need_rank >= ex && need_rank < ex + myc) {
            int need = need_rank - ex;
#pragma unroll
            for (int w2 = 0; w2 < 2; w2++) {
                int word = (w2 == 0) ? w0 : w1;
#pragma unroll
                for (int b = 0; b < 4; b++) {
                    int v = (word >> (8 * b)) & 0xFF;
                    int ff = v & 3;
                    bool hit = (mode == 0) ? (ff == 1) : (mode == 1) ? (ff == 2) : (ff != 2);
                    if (hit) {
                        if (need == 0) {
                            int idx = c * 256 + lane * 8 + w2 * 4 + b;
                            ent = idx | ((v >> 2) << 16);
                        }
                        need--;
                    }
                }
            }
        }
#pragma unroll
        for (int o = 16; o; o >>= 1) ent |= __shfl_xor_sync(full, ent, o);

        const int idx = ent & 0xFFFF;
        const int g   = (ent >> 16) & 0x3F;
        const int lbl = is_pos ? slbl[g] : 0;

        // issue regression loads EARLY (lane 0) so they overlap the softmax
        float4 pp = make_float4(0.f, 0.f, 0.f, 0.f);
        float4 pv = make_float4(0.f, 0.f, 0.f, 0.f);
        if (lane == 0 && is_pos) {
            pp = ((const float4*)props)[idx];
            pv = *(const float4*)(txty + ((size_t)idx * NCLS + g) * 4);
        }

        const float* row = score + (size_t)idx * NCLS;
        float v0 = row[lane];
        float v1 = row[lane + 32];
        float v2 = (lane + 64 < NCLS) ? row[lane + 64] : -INFINITY;
        float m = fmaxf(fmaxf(v0, v1), v2);
#pragma unroll
        for (int o = 16; o; o >>= 1) m = fmaxf(m, __shfl_xor_sync(full, m, o));
        float s = expf(v0 - m) + expf(v1 - m) + ((lane + 64 < NCLS) ? expf(v2 - m) : 0.0f);
#pragma unroll
        for (int o = 16; o; o >>= 1) s += __shfl_xor_sync(full, s, o);

        float cand = (lbl < 32) ? v0 : ((lbl < 64) ? v1 : v2);
        float vl = __shfl_sync(full, cand, lbl & 31);

        if (lane == 0) {
            float ce = m + logf(s) - vl;
            float rg = 0.0f;
            if (is_pos) {
                float4 gb = sg[g];
                float pw = pp.z - pp.x, ph = pp.w - pp.y;
                float pcx = pp.x + 0.5f * pw, pcy = pp.y + 0.5f * ph;
                float gw = gb.z - gb.x, gh = gb.w - gb.y;
                float gcx = gb.x + 0.5f * gw, gcy = gb.y + 0.5f * gh;
                float t0 = ((gcx - pcx) / pw) * 10.0f;
                float t1 = ((gcy - pcy) / ph) * 10.0f;
                float t2 = logf(gw / pw) * 5.0f;
                float t3 = logf(gh / ph) * 5.0f;
                rg = sl1(pv.x - t0) + sl1(pv.y - t1) + sl1(pv.z - t2) + sl1(pv.w - t3);
            }
            // fixed-point (2^32) deterministic accumulation; both values >= 0
            unsigned long long ece = __double2ull_rn((double)ce * 4294967296.0);
            unsigned long long erg = __double2ull_rn((double)rg * 4294967296.0);
            atomicAdd(&g_acc_ce, ece);
            atomicAdd(&g_acc_rg, erg);
        }
    }

    // ============ ticket: last block writes out, resets state ============
    __syncthreads();
    if (t == 0) {
        __threadfence();
        s_last = (atomicAdd(&g_done, 1) == NBLK - 1) ? 1 : 0;
    }
    __syncthreads();
    if (s_last && t == 0) {
        __threadfence();
        unsigned long long ace = g_acc_ce;
        unsigned long long arg = g_acc_rg;
        out[0] = (float)((double)ace / 4294967296.0 / (double)TOTAL);
        out[1] = (float)((double)arg / 4294967296.0 / (double)TOTAL);
        // reset for next graph replay
        g_acc_ce = 0ull;
        g_acc_rg = 0ull;
        g_cntA[0] = 0; g_genA[0] = 0; g_done = 0;
    }
}

extern "C" void kernel_launch(void* const* d_in, const int* in_sizes, int n_in,
                              void* d_out, int out_size) {
    const float* props = (const float*)d_in[1];
    const float* score = (const float*)d_in[2];
    const float* txty  = (const float*)d_in[3];
    const float* gts   = (const float*)d_in[4];
    const int*   glbl  = (const int*)d_in[5];
    float* out = (float*)d_out;

    k_fused<<<NBLK, TPB>>>(props, gts, glbl, score, txty, out);
}

// round 16
// speedup vs baseline: 1.1382x; 1.1382x over previous
#include <cuda_runtime.h>
#include <cuda_bf16.h>
#include <math.h>

#define N_PROP   65536
#define N_GT     64
#define NCLS     81
#define TOTAL    512
#define MAX_POS  128
#define K1_TPB   1024
#define K1_NBLK  128
#define PPB      512
#define NCHUNK   256            // chunks of 256 proposals
#define K2_TPB   256
#define K2_NBLK  128            // 4 warps loss -> 512 slots

// -------- device scratch --------
__device__ unsigned char g_resb[N_PROP];   // f | (gt<<2)
__device__ int   g_ckp[NCHUNK];
__device__ int   g_ckn[NCHUNK];
__device__ float g_ce[TOTAL];
__device__ float g_rg[TOTAL];
__device__ int   g_done;

__device__ __forceinline__ float sl1(float d) {
    float ad = fabsf(d);
    return (ad < 1.0f) ? (0.5f * d * d) : (ad - 0.5f);
}

// ================= K1: IoU + classify + chunk counts (proven) =================
__global__ void __launch_bounds__(K1_TPB, 1)
k_iou(const float* __restrict__ props, const float* __restrict__ gts) {
    __shared__ float4 sg[N_GT];
    __shared__ float  sS[N_GT];
    __shared__ float  sga[N_GT];
    __shared__ float  s_ci[PPB], s_cu[PPB];
    __shared__ int    s_cj[PPB];
    __shared__ int    wpc[16], wnc[16];

    const int t    = threadIdx.x;
    const int bid  = blockIdx.x;
    const int warp = t >> 5, lane = t & 31;
    const int half = t >> 9;
    const int lp   = t & (PPB - 1);
    const unsigned full = 0xffffffffu;

    if (t < N_GT) {
        float4 g = ((const float4*)gts)[t];
        float ga = (g.z - g.x) * (g.w - g.y);
        sg[t]  = g;
        sga[t] = ga;
        sS[t]  = ga + 1e-8f;
    }
    __syncthreads();

    const int i = bid * PPB + lp;
    const float4 p = ((const float4*)props)[i];
    const float pa = (p.z - p.x) * (p.w - p.y);

    const int j0 = half * 32;
    float biA, bSA, biB, bSB;
    int   bjA, bjB;
    {
        float4 g = sg[j0];
        float ix = fmaxf(fminf(p.z, g.z) - fmaxf(p.x, g.x), 0.f);
        float iy = fmaxf(fminf(p.w, g.w) - fmaxf(p.y, g.y), 0.f);
        biA = ix * iy; bSA = pa + sS[j0]; bjA = j0;
        g = sg[j0 + 16];
        ix = fmaxf(fminf(p.z, g.z) - fmaxf(p.x, g.x), 0.f);
        iy = fmaxf(fminf(p.w, g.w) - fmaxf(p.y, g.y), 0.f);
        biB = ix * iy; bSB = pa + sS[j0 + 16]; bjB = j0 + 16;
    }
#pragma unroll
    for (int j = 1; j < 16; j++) {
        int jA = j0 + j, jB = j0 + 16 + j;
        float4 gA = sg[jA], gB = sg[jB];
        float SA = pa + sS[jA], SB = pa + sS[jB];
        float ixA = fmaxf(fminf(p.z, gA.z) - fmaxf(p.x, gA.x), 0.f);
        float iyA = fmaxf(fminf(p.w, gA.w) - fmaxf(p.y, gA.y), 0.f);
        float ixB = fmaxf(fminf(p.z, gB.z) - fmaxf(p.x, gB.x), 0.f);
        float iyB = fmaxf(fminf(p.w, gB.w) - fmaxf(p.y, gB.y), 0.f);
        float inA = ixA * iyA, inB = ixB * iyB;
        // iou_new > iou_best <=> in*bS > bi*S (union -inter terms cancel exactly)
        if (inA * bSA > biA * SA) { biA = inA; bSA = SA; bjA = jA; }
        if (inB * bSB > biB * SB) { biB = inB; bSB = SB; bjB = jB; }
    }
    if (biB * bSA > biA * bSB) { biA = biB; bSA = bSB; bjA = bjB; }

    if (half == 1) { s_ci[lp] = biA; s_cu[lp] = bSA; s_cj[lp] = bjA; }
    __syncthreads();

    int f = 0;
    unsigned bp = 0, bn = 0;
    if (half == 0) {
        float ui = s_ci[lp], uS = s_cu[lp];
        if (ui * bSA > biA * uS) { biA = ui; bSA = uS; bjA = s_cj[lp]; }
        float u = ((pa + sga[bjA]) - biA) + 1e-8f;   // exact reference assoc order
        float miou = biA / u;
        f = (miou >= 0.5f) ? 1 : ((miou >= 0.1f) ? 2 : 0);
        g_resb[i] = (unsigned char)(f | (bjA << 2));
        bp = __ballot_sync(full, f == 1);
        bn = __ballot_sync(full, f == 2);
        if (lane == 0) { wpc[warp] = __popc(bp); wnc[warp] = __popc(bn); }
    }
    __syncthreads();
    if (t < 2) {        // chunk counts: warps 0-7 -> chunk 2bid, 8-15 -> 2bid+1
        int cp = 0, cn = 0;
#pragma unroll
        for (int w = 0; w < 8; w++) { cp += wpc[t * 8 + w]; cn += wnc[t * 8 + w]; }
        g_ckp[2 * bid + t] = cp;
        g_ckn[2 * bid + t] = cn;
    }
}

// ======== K2: scan + resolve + loss + ticket reduce (R14 post-barrier) ========
__global__ void __launch_bounds__(K2_TPB)
k_loss(const float* __restrict__ props,
       const float* __restrict__ gts,
       const int*   __restrict__ gt_labels,
       const float* __restrict__ score,
       const float* __restrict__ txty,
       float* __restrict__ out) {
    __shared__ float4 sg[N_GT];
    __shared__ int    slbl[N_GT];
    __shared__ int    swp[8], swn[8];
    __shared__ int    ssp[NCHUNK], ssn[NCHUNK];
    __shared__ int    s_numpos, s_negtot;
    __shared__ int    s_last;
    __shared__ float  rc[8], rr[8];

    const int t    = threadIdx.x;
    const int bid  = blockIdx.x;
    const int warp = t >> 5, lane = t & 31;
    const unsigned full = 0xffffffffu;

    if (t < N_GT) {
        sg[t] = ((const float4*)gts)[t];
        slbl[t] = gt_labels[t];
    }

    // ---- scan 256 chunk counts (all 8 warps; data ready at kernel entry) ----
    {
        int ip  = __ldcg(&g_ckp[t]);
        int in_ = __ldcg(&g_ckn[t]);
#pragma unroll
        for (int o = 1; o < 32; o <<= 1) {
            int a = __shfl_up_sync(full, ip, o);
            int b = __shfl_up_sync(full, in_, o);
            if (lane >= o) { ip += a; in_ += b; }
        }
        if (lane == 31) { swp[warp] = ip; swn[warp] = in_; }
        __syncthreads();
        int basep = 0, basen = 0;
        for (int w = 0; w < warp; w++) { basep += swp[w]; basen += swn[w]; }
        ssp[t] = basep + ip;
        ssn[t] = basen + in_;
    }
    __syncthreads();
    if (t == 0) {
        s_numpos = min(ssp[NCHUNK - 1], MAX_POS);
        s_negtot = ssn[NCHUNK - 1];
    }
    __syncthreads();

    // ---- resolve + loss: warps 0-3 own slots 4bid+w ----
    if (warp < 4) {
        const int slot = bid * 4 + warp;
        const int npos = s_numpos, negt = s_negtot;
        int mode, r;
        bool is_pos = slot < npos;
        if (is_pos)                  { mode = 0; r = slot; }
        else if (slot < npos + negt) { mode = 1; r = slot - npos; }
        else                         { mode = 2; r = slot - npos - negt; }

        // find owning chunk (lane-parallel over 256 chunks)
        int found = 0;
#pragma unroll
        for (int k = 0; k < 8; k++) {
            int c = lane + 32 * k;
            int sp0 = (c > 0) ? ssp[c - 1] : 0;
            int sn0 = (c > 0) ? ssn[c - 1] : 0;
            int cb, ce_;
            if (mode == 0)      { cb = sp0;           ce_ = ssp[c]; }
            else if (mode == 1) { cb = sn0;           ce_ = ssn[c]; }
            else                { cb = c * 256 - sn0; ce_ = (c + 1) * 256 - ssn[c]; }
            if (cb <= r && r < ce_) found = c + 1;
        }
#pragma unroll
        for (int o = 16; o; o >>= 1) found = max(found, __shfl_xor_sync(full, found, o));
        const int c = found - 1;
        int cb;
        {
            int sp0 = (c > 0) ? ssp[c - 1] : 0;
            int sn0 = (c > 0) ? ssn[c - 1] : 0;
            cb = (mode == 0) ? sp0 : (mode == 1) ? sn0 : (c * 256 - sn0);
        }
        const int need_rank = r - cb;

        // load chunk flags: 256 bytes = 64 ints; lane l takes words 2l, 2l+1
        const int* cw = (const int*)g_resb + c * 64;
        int w0 = __ldcg(&cw[2 * lane]);
        int w1 = __ldcg(&cw[2 * lane + 1]);
        int myc;
        if (mode == 0)      myc = __popc(w0 & 0x01010101) + __popc(w1 & 0x01010101);
        else if (mode == 1) myc = __popc(w0 & 0x02020202) + __popc(w1 & 0x02020202);
        else                myc = 8 - __popc(w0 & 0x02020202) - __popc(w1 & 0x02020202);
        int ex = myc;
#pragma unroll
        for (int o = 1; o < 32; o <<= 1) {
            int a = __shfl_up_sync(full, ex, o);
            if (lane >= o) ex += a;
        }
        ex -= myc;
        int ent = 0;
        if (need_rank >= ex && need_rank < ex + myc) {
            int need = need_rank - ex;
#pragma unroll
            for (int w2 = 0; w2 < 2; w2++) {
                int word = (w2 == 0) ? w0 : w1;
#pragma unroll
                for (int b = 0; b < 4; b++) {
                    int v = (word >> (8 * b)) & 0xFF;
                    int ff = v & 3;
                    bool hit = (mode == 0) ? (ff == 1) : (mode == 1) ? (ff == 2) : (ff != 2);
                    if (hit) {
                        if (need == 0) {
                            int idx = c * 256 + lane * 8 + w2 * 4 + b;
                            ent = idx | ((v >> 2) << 16);
                        }
                        need--;
                    }
                }
            }
        }
#pragma unroll
        for (int o = 16; o; o >>= 1) ent |= __shfl_xor_sync(full, ent, o);

        const int idx = ent & 0xFFFF;
        const int g   = (ent >> 16) & 0x3F;
        const int lbl = is_pos ? slbl[g] : 0;

        const float* row = score + (size_t)idx * NCLS;
        float v0 = row[lane];
        float v1 = row[lane + 32];
        float v2 = (lane + 64 < NCLS) ? row[lane + 64] : -INFINITY;
        float m = fmaxf(fmaxf(v0, v1), v2);
#pragma unroll
        for (int o = 16; o; o >>= 1) m = fmaxf(m, __shfl_xor_sync(full, m, o));
        float s = expf(v0 - m) + expf(v1 - m) + ((lane + 64 < NCLS) ? expf(v2 - m) : 0.0f);
#pragma unroll
        for (int o = 16; o; o >>= 1) s += __shfl_xor_sync(full, s, o);

        float cand = (lbl < 32) ? v0 : ((lbl < 64) ? v1 : v2);
        float vl = __shfl_sync(full, cand, lbl & 31);

        if (lane == 0) {
            float ce = m + logf(s) - vl;
            float rg = 0.0f;
            if (is_pos) {
                float4 pp = ((const float4*)props)[idx];
                float4 gb = sg[g];
                float pw = pp.z - pp.x, ph = pp.w - pp.y;
                float pcx = pp.x + 0.5f * pw, pcy = pp.y + 0.5f * ph;
                float gw = gb.z - gb.x, gh = gb.w - gb.y;
                float gcx = gb.x + 0.5f * gw, gcy = gb.y + 0.5f * gh;
                float t0 = ((gcx - pcx) / pw) * 10.0f;
                float t1 = ((gcy - pcy) / ph) * 10.0f;
                float t2 = logf(gw / pw) * 5.0f;
                float t3 = logf(gh / ph) * 5.0f;
                float4 pv = *(const float4*)(txty + ((size_t)idx * NCLS + g) * 4);
                rg = sl1(pv.x - t0) + sl1(pv.y - t1) + sl1(pv.z - t2) + sl1(pv.w - t3);
            }
            g_ce[slot] = ce;
            g_rg[slot] = rg;
        }
    }

    // ---- ticket: last-arriving block reduces, resets state ----
    __syncthreads();
    if (t == 0) {
        __threadfence();
        s_last = (atomicAdd(&g_done, 1) == K2_NBLK - 1) ? 1 : 0;
    }
    __syncthreads();
    if (s_last) {
        __threadfence();
        float c  = __ldcg(&g_ce[t])   + __ldcg(&g_ce[t + 256]);
        float r2 = __ldcg(&g_rg[t])   + __ldcg(&g_rg[t + 256]);
#pragma unroll
        for (int o = 16; o; o >>= 1) {
            c  += __shfl_xor_sync(full, c, o);
            r2 += __shfl_xor_sync(full, r2, o);
        }
        if (lane == 0) { rc[warp] = c; rr[warp] = r2; }
        __syncthreads();
        if (warp == 0) {
            float cc  = (lane < 8) ? rc[lane] : 0.0f;
            float rrv = (lane < 8) ? rr[lane] : 0.0f;
#pragma unroll
            for (int o = 4; o; o >>= 1) {
                cc  += __shfl_xor_sync(full, cc, o);
                rrv += __shfl_xor_sync(full, rrv, o);
            }
            if (lane == 0) {
                out[0] = cc  * (1.0f / (float)TOTAL);
                out[1] = rrv * (1.0f / (float)TOTAL);
                g_done = 0;     // reset for next graph replay
            }
        }
    }
}

extern "C" void kernel_launch(void* const* d_in, const int* in_sizes, int n_in,
                              void* d_out, int out_size) {
    const float* props = (const float*)d_in[1];
    const float* score = (const float*)d_in[2];
    const float* txty  = (const float*)d_in[3];
    const float* gts   = (const float*)d_in[4];
    const int*   glbl  = (const int*)d_in[5];
    float* out = (float*)d_out;

    k_iou <<<K1_NBLK, K1_TPB>>>(props, gts);
    k_loss<<<K2_NBLK, K2_TPB>>>(props, gts, glbl, score, txty, out);
}

// round 17
// speedup vs baseline: 1.1407x; 1.0022x over previous
#include <cuda_runtime.h>
#include <cuda_bf16.h>
#include <math.h>

#define N_PROP   65536
#define N_GT     64
#define NCLS     81
#define TOTAL    512
#define MAX_POS  128
#define K1_TPB   1024
#define K1_NBLK  128
#define PPB      512
#define NCHUNK   256            // chunks of 256 proposals
#define K2_TPB   256
#define K2_NBLK  128            // 4 warps loss -> 512 slots

// -------- device scratch --------
__device__ unsigned char g_resb[N_PROP];   // f | (gt<<2)
__device__ int   g_ckp[NCHUNK];
__device__ int   g_ckn[NCHUNK];
__device__ float g_ce[TOTAL];
__device__ float g_rg[TOTAL];
__device__ int   g_done;

__device__ __forceinline__ float sl1(float d) {
    float ad = fabsf(d);
    return (ad < 1.0f) ? (0.5f * d * d) : (ad - 0.5f);
}

// ====== K1: IoU + classify. 4 thr/prop x 16 gts, 2 props/thread (LDS/2) ======
__global__ void __launch_bounds__(K1_TPB, 1)
k_iou(const float* __restrict__ props, const float* __restrict__ gts) {
    __shared__ float4 sg[N_GT];
    __shared__ float  sS[N_GT];       // ga + 1e-8 (comparison fold)
    __shared__ float  sga[N_GT];      // raw ga (exact final union)
    __shared__ float  q_ci[3][PPB], q_cu[3][PPB];
    __shared__ int    q_cj[3][PPB];
    __shared__ int    wpcA[8], wncA[8], wpcB[8], wncB[8];

    const int t = threadIdx.x, bid = blockIdx.x;
    const int warp = t >> 5, lane = t & 31;
    const int q  = t >> 8;            // quarter 0..3 -> gts [16q, 16q+16)
    const int lp = t & 255;
    const unsigned full = 0xffffffffu;

    if (t < N_GT) {
        float4 g = ((const float4*)gts)[t];
        float ga = (g.z - g.x) * (g.w - g.y);
        sg[t]  = g;
        sga[t] = ga;
        sS[t]  = ga + 1e-8f;
    }
    __syncthreads();

    // two proposals per thread
    const int i0 = bid * PPB + lp;
    const int i1 = i0 + 256;
    const float4 p0 = ((const float4*)props)[i0];
    const float4 p1 = ((const float4*)props)[i1];
    const float pa0 = (p0.z - p0.x) * (p0.w - p0.y);
    const float pa1 = (p1.z - p1.x) * (p1.w - p1.y);

    const int j0 = q * 16;
    float bi0, bS0, bi1, bS1;
    int   bj0, bj1;
    {
        float4 g = sg[j0]; float Sg = sS[j0];
        float ix0 = fmaxf(fminf(p0.z, g.z) - fmaxf(p0.x, g.x), 0.f);
        float iy0 = fmaxf(fminf(p0.w, g.w) - fmaxf(p0.y, g.y), 0.f);
        bi0 = ix0 * iy0; bS0 = pa0 + Sg; bj0 = j0;
        float ix1 = fmaxf(fminf(p1.z, g.z) - fmaxf(p1.x, g.x), 0.f);
        float iy1 = fmaxf(fminf(p1.w, g.w) - fmaxf(p1.y, g.y), 0.f);
        bi1 = ix1 * iy1; bS1 = pa1 + Sg; bj1 = j0;
    }
#pragma unroll
    for (int j = j0 + 1; j < j0 + 16; j++) {
        float4 g = sg[j]; float Sg = sS[j];
        float ix0 = fmaxf(fminf(p0.z, g.z) - fmaxf(p0.x, g.x), 0.f);
        float iy0 = fmaxf(fminf(p0.w, g.w) - fmaxf(p0.y, g.y), 0.f);
        float ix1 = fmaxf(fminf(p1.z, g.z) - fmaxf(p1.x, g.x), 0.f);
        float iy1 = fmaxf(fminf(p1.w, g.w) - fmaxf(p1.y, g.y), 0.f);
        float in0 = ix0 * iy0, in1 = ix1 * iy1;
        float S0 = pa0 + Sg,   S1 = pa1 + Sg;
        // iou_new > iou_best <=> in*bS > bi*S (union -inter terms cancel exactly)
        if (in0 * bS0 > bi0 * S0) { bi0 = in0; bS0 = S0; bj0 = j; }
        if (in1 * bS1 > bi1 * S1) { bi1 = in1; bS1 = S1; bj1 = j; }
    }
    if (q) {
        q_ci[q - 1][lp]       = bi0; q_cu[q - 1][lp]       = bS0; q_cj[q - 1][lp]       = bj0;
        q_ci[q - 1][lp + 256] = bi1; q_cu[q - 1][lp + 256] = bS1; q_cj[q - 1][lp + 256] = bj1;
    }
    __syncthreads();

    if (q == 0) {
        // fold quarters 1..3 in gt-index order: strictly greater wins -> first argmax
#pragma unroll
        for (int k = 0; k < 3; k++) {
            float ci = q_ci[k][lp], cu = q_cu[k][lp];
            int   cj = q_cj[k][lp];
            if (ci * bS0 > bi0 * cu) { bi0 = ci; bS0 = cu; bj0 = cj; }
            ci = q_ci[k][lp + 256]; cu = q_cu[k][lp + 256]; cj = q_cj[k][lp + 256];
            if (ci * bS1 > bi1 * cu) { bi1 = ci; bS1 = cu; bj1 = cj; }
        }
        // exact final iou in reference association order
        float u0 = ((pa0 + sga[bj0]) - bi0) + 1e-8f;
        float u1 = ((pa1 + sga[bj1]) - bi1) + 1e-8f;
        float m0 = bi0 / u0;
        float m1 = bi1 / u1;
        int f0 = (m0 >= 0.5f) ? 1 : ((m0 >= 0.1f) ? 2 : 0);
        int f1 = (m1 >= 0.5f) ? 1 : ((m1 >= 0.1f) ? 2 : 0);
        g_resb[i0] = (unsigned char)(f0 | (bj0 << 2));
        g_resb[i1] = (unsigned char)(f1 | (bj1 << 2));

        unsigned bpA = __ballot_sync(full, f0 == 1);
        unsigned bnA = __ballot_sync(full, f0 == 2);
        unsigned bpB = __ballot_sync(full, f1 == 1);
        unsigned bnB = __ballot_sync(full, f1 == 2);
        if (lane == 0) {
            wpcA[warp] = __popc(bpA); wncA[warp] = __popc(bnA);
            wpcB[warp] = __popc(bpB); wncB[warp] = __popc(bnB);
        }
    }
    __syncthreads();
    if (t < 2) {        // chunk 2bid = props [0,256), chunk 2bid+1 = [256,512)
        int cp = 0, cn = 0;
#pragma unroll
        for (int w = 0; w < 8; w++) {
            cp += (t == 0) ? wpcA[w] : wpcB[w];
            cn += (t == 0) ? wncA[w] : wncB[w];
        }
        g_ckp[2 * bid + t] = cp;
        g_ckn[2 * bid + t] = cn;
    }
}

// ======== K2: scan + resolve + loss + ticket reduce (R16 proven, unchanged) ===
__global__ void __launch_bounds__(K2_TPB)
k_loss(const float* __restrict__ props,
       const float* __restrict__ gts,
       const int*   __restrict__ gt_labels,
       const float* __restrict__ score,
       const float* __restrict__ txty,
       float* __restrict__ out) {
    __shared__ float4 sg[N_GT];
    __shared__ int    slbl[N_GT];
    __shared__ int    swp[8], swn[8];
    __shared__ int    ssp[NCHUNK], ssn[NCHUNK];
    __shared__ int    s_numpos, s_negtot;
    __shared__ int    s_last;
    __shared__ float  rc[8], rr[8];

    const int t    = threadIdx.x;
    const int bid  = blockIdx.x;
    const int warp = t >> 5, lane = t & 31;
    const unsigned full = 0xffffffffu;

    if (t < N_GT) {
        sg[t] = ((const float4*)gts)[t];
        slbl[t] = gt_labels[t];
    }

    // ---- scan 256 chunk counts ----
    {
        int ip  = __ldcg(&g_ckp[t]);
        int in_ = __ldcg(&g_ckn[t]);
#pragma unroll
        for (int o = 1; o < 32; o <<= 1) {
            int a = __shfl_up_sync(full, ip, o);
            int b = __shfl_up_sync(full, in_, o);
            if (lane >= o) { ip += a; in_ += b; }
        }
        if (lane == 31) { swp[warp] = ip; swn[warp] = in_; }
        __syncthreads();
        int basep = 0, basen = 0;
        for (int w = 0; w < warp; w++) { basep += swp[w]; basen += swn[w]; }
        ssp[t] = basep + ip;
        ssn[t] = basen + in_;
    }
    __syncthreads();
    if (t == 0) {
        s_numpos = min(ssp[NCHUNK - 1], MAX_POS);
        s_negtot = ssn[NCHUNK - 1];
    }
    __syncthreads();

    // ---- resolve + loss: warps 0-3 own slots 4bid+w ----
    if (warp < 4) {
        const int slot = bid * 4 + warp;
        const int npos = s_numpos, negt = s_negtot;
        int mode, r;
        bool is_pos = slot < npos;
        if (is_pos)                  { mode = 0; r = slot; }
        else if (slot < npos + negt) { mode = 1; r = slot - npos; }
        else                         { mode = 2; r = slot - npos - negt; }

        int found = 0;
#pragma unroll
        for (int k = 0; k < 8; k++) {
            int c = lane + 32 * k;
            int sp0 = (c > 0) ? ssp[c - 1] : 0;
            int sn0 = (c > 0) ? ssn[c - 1] : 0;
            int cb, ce_;
            if (mode == 0)      { cb = sp0;           ce_ = ssp[c]; }
            else if (mode == 1) { cb = sn0;           ce_ = ssn[c]; }
            else                { cb = c * 256 - sn0; ce_ = (c + 1) * 256 - ssn[c]; }
            if (cb <= r && r < ce_) found = c + 1;
        }
#pragma unroll
        for (int o = 16; o; o >>= 1) found = max(found, __shfl_xor_sync(full, found, o));
        const int c = found - 1;
        int cb;
        {
            int sp0 = (c > 0) ? ssp[c - 1] : 0;
            int sn0 = (c > 0) ? ssn[c - 1] : 0;
            cb = (mode == 0) ? sp0 : (mode == 1) ? sn0 : (c * 256 - sn0);
        }
        const int need_rank = r - cb;

        const int* cw = (const int*)g_resb + c * 64;
        int w0 = __ldcg(&cw[2 * lane]);
        int w1 = __ldcg(&cw[2 * lane + 1]);
        int myc;
        if (mode == 0)      myc = __popc(w0 & 0x01010101) + __popc(w1 & 0x01010101);
        else if (mode == 1) myc = __popc(w0 & 0x02020202) + __popc(w1 & 0x02020202);
        else                myc = 8 - __popc(w0 & 0x02020202) - __popc(w1 & 0x02020202);
        int ex = myc;
#pragma unroll
        for (int o = 1; o < 32; o <<= 1) {
            int a = __shfl_up_sync(full, ex, o);
            if (lane >= o) ex += a;
        }
        ex -= myc;
        int ent = 0;
        if (need_rank >= ex && need_rank < ex + myc) {
            int need = need_rank - ex;
#pragma unroll
            for (int w2 = 0; w2 < 2; w2++) {
                int word = (w2 == 0) ? w0 : w1;
#pragma unroll
                for (int b = 0; b < 4; b++) {
                    int v = (word >> (8 * b)) & 0xFF;
                    int ff = v & 3;
                    bool hit = (mode == 0) ? (ff == 1) : (mode == 1) ? (ff == 2) : (ff != 2);
                    if (hit) {
                        if (need == 0) {
                            int idx = c * 256 + lane * 8 + w2 * 4 + b;
                            ent = idx | ((v >> 2) << 16);
                        }
                        need--;
                    }
                }
            }
        }
#pragma unroll
        for (int o = 16; o; o >>= 1) ent |= __shfl_xor_sync(full, ent, o);

        const int idx = ent & 0xFFFF;
        const int g   = (ent >> 16) & 0x3F;
        const int lbl = is_pos ? slbl[g] : 0;

        const float* row = score + (size_t)idx * NCLS;
        float v0 = row[lane];
        float v1 = row[lane + 32];
        float v2 = (lane + 64 < NCLS) ? row[lane + 64] : -INFINITY;
        float m = fmaxf(fmaxf(v0, v1), v2);
#pragma unroll
        for (int o = 16; o; o >>= 1) m = fmaxf(m, __shfl_xor_sync(full, m, o));
        float s = expf(v0 - m) + expf(v1 - m) + ((lane + 64 < NCLS) ? expf(v2 - m) : 0.0f);
#pragma unroll
        for (int o = 16; o; o >>= 1) s += __shfl_xor_sync(full, s, o);

        float cand = (lbl < 32) ? v0 : ((lbl < 64) ? v1 : v2);
        float vl = __shfl_sync(full, cand, lbl & 31);

        if (lane == 0) {
            float ce = m + logf(s) - vl;
            float rg = 0.0f;
            if (is_pos) {
                float4 pp = ((const float4*)props)[idx];
                float4 gb = sg[g];
                float pw = pp.z - pp.x, ph = pp.w - pp.y;
                float pcx = pp.x + 0.5f * pw, pcy = pp.y + 0.5f * ph;
                float gw = gb.z - gb.x, gh = gb.w - gb.y;
                float gcx = gb.x + 0.5f * gw, gcy = gb.y + 0.5f * gh;
                float t0 = ((gcx - pcx) / pw) * 10.0f;
                float t1 = ((gcy - pcy) / ph) * 10.0f;
                float t2 = logf(gw / pw) * 5.0f;
                float t3 = logf(gh / ph) * 5.0f;
                float4 pv = *(const float4*)(txty + ((size_t)idx * NCLS + g) * 4);
                rg = sl1(pv.x - t0) + sl1(pv.y - t1) + sl1(pv.z - t2) + sl1(pv.w - t3);
            }
            g_ce[slot] = ce;
            g_rg[slot] = rg;
        }
    }

    // ---- ticket: last-arriving block reduces, resets state ----
    __syncthreads();
    if (t == 0) {
        __threadfence();
        s_last = (atomicAdd(&g_done, 1) == K2_NBLK - 1) ? 1 : 0;
    }
    __syncthreads();
    if (s_last) {
        __threadfence();
        float c  = __ldcg(&g_ce[t])   + __ldcg(&g_ce[t + 256]);
        float r2 = __ldcg(&g_rg[t])   + __ldcg(&g_rg[t + 256]);
#pragma unroll
        for (int o = 16; o; o >>= 1) {
            c  += __shfl_xor_sync(full, c, o);
            r2 += __shfl_xor_sync(full, r2, o);
        }
        if (lane == 0) { rc[warp] = c; rr[warp] = r2; }
        __syncthreads();
        if (warp == 0) {
            float cc  = (lane < 8) ? rc[lane] : 0.0f;
            float rrv = (lane < 8) ? rr[lane] : 0.0f;
#pragma unroll
            for (int o = 4; o; o >>= 1) {
                cc  += __shfl_xor_sync(full, cc, o);
                rrv += __shfl_xor_sync(full, rrv, o);
            }
            if (lane == 0) {
                out[0] = cc  * (1.0f / (float)TOTAL);
                out[1] = rrv * (1.0f / (float)TOTAL);
                g_done = 0;     // reset for next graph replay
            }
        }
    }
}

extern "C" void kernel_launch(void* const* d_in, const int* in_sizes, int n_in,
                              void* d_out, int out_size) {
    const float* props = (const float*)d_in[1];
    const float* score = (const float*)d_in[2];
    const float* txty  = (const float*)d_in[3];
    const float* gts   = (const float*)d_in[4];
    const int*   glbl  = (const int*)d_in[5];
    float* out = (float*)d_out;

    k_iou <<<K1_NBLK, K1_TPB>>>(props, gts);
    k_loss<<<K2_NBLK, K2_TPB>>>(props, gts, glbl, score, txty, out);
}